// round 15
// baseline (speedup 1.0000x reference)
#include <cuda_runtime.h>
#include <cuda_fp16.h>
#include <cstdint>

// Problem dims
#define B_ 16
#define S_ 256
#define V_ 32000
#define H_ 1024

// ---------------- scratch (device globals — no runtime alloc) ----------------
__device__ __align__(256) float  g_hbuf[2][B_ * H_];              // ping-pong hidden state
__device__ __align__(256) __half g_Hall[B_ * S_ * H_];            // all h_t, fp16 (8 MB)
__device__ __align__(256) __half g_W16[(size_t)V_ * H_];          // Why in fp16 (64 MB)
__device__ __align__(256) int g_bar[4 * 32];                      // 4 monotonic group counters, 128B apart

// ---------------- helpers ----------------
__device__ __forceinline__ uint32_t smem_u32(const void* p) {
    uint32_t a;
    asm("{ .reg .u64 t; cvta.to.shared.u64 t, %1; cvt.u32.u64 %0, t; }" : "=r"(a) : "l"(p));
    return a;
}
#define SW128(off) ((off) ^ (((off) >> 3) & 0x70))

__device__ __forceinline__ void ffma2(unsigned long long& d, unsigned long long a,
                                      unsigned long long b) {
    asm("fma.rn.f32x2 %0, %1, %2, %0;" : "+l"(d) : "l"(a), "l"(b));
}
__device__ __forceinline__ float unpack_sum(unsigned long long v) {
    float lo, hi;
    asm("mov.b64 {%0, %1}, %2;" : "=f"(lo), "=f"(hi) : "l"(v));
    return lo + hi;
}

__device__ __forceinline__ float fw_tanh(float x) {
    const float BP = 8192.0f / 32767.0f;
    float xc = fminf(fmaxf(x, -1.0f), 1.0f);
    float a = fabsf(xc);
    return (a < BP) ? xc : copysignf(BP + (a - BP) * 0.75f, xc);
}

// ---------------- kernel: init (zero the 4 group counters only) -------------
__global__ void init_kernel() {
    int i = blockIdx.x * blockDim.x + threadIdx.x;
    if (i < 4 * 32) g_bar[i] = 0;
}

// ---------------- persistent recurrence kernel (v11) -------------------------
// Grid 148 CTAs x 256 threads (1/SM).
//   CTAs 0..127 : recurrence. CTA c: batch group bgrp=c&3, row group rgrp=c>>2.
//                 Monotonic per-group counters; tid0 release-arrive + poll.
//   CTAs 128..147: convert Why -> fp16 (g_W16) on otherwise-idle SMs, then exit.
//                 Kernel-end ordering makes g_W16 visible to the GEMM.
// t=0 uses zeros written to smem directly (h0 == 0), so g_hbuf needs no init.
#define RNN_CTAS 128
#define CVT_CTAS 20

__global__ __launch_bounds__(256, 1) void rnn_persist(const int* __restrict__ x_seq,
                                                      const float* __restrict__ Wxh,
                                                      const float* __restrict__ Whh,
                                                      const float* __restrict__ Why,
                                                      float* __restrict__ out_tail) {
    extern __shared__ float sm[];
    ulonglong2* hsm2 = (ulonglong2*)sm;          // [4][256] 16B units

    const int c    = blockIdx.x;
    const int tid  = threadIdx.x;

    // ---- spare-SM path: Why -> fp16 conversion ----
    if (c >= RNN_CTAS) {
        const size_t n4 = (size_t)V_ * H_ / 4;
        const float4* in = (const float4*)Why;
        __half2* o16 = (__half2*)g_W16;
        for (size_t i = (size_t)(c - RNN_CTAS) * 256 + tid; i < n4;
             i += (size_t)CVT_CTAS * 256) {
            float4 v = __ldg(&in[i]);
            o16[2 * i]     = __floats2half2_rn(v.x, v.y);
            o16[2 * i + 1] = __floats2half2_rn(v.z, v.w);
        }
        return;
    }

    // ---- recurrence path ----
    const int w    = tid >> 5;
    const int l    = tid & 31;
    const int bgrp = c & 3;        // batches bgrp*4 .. bgrp*4+3
    const int rgrp = c >> 2;       // rows rgrp*32 .. rgrp*32+31

    // Whh slice -> registers: 4 rows x 8 k-units (16B each) = 128 regs
    ulonglong2 wreg[4][8];
#pragma unroll
    for (int r = 0; r < 4; r++) {
        const ulonglong2* Wg =
            (const ulonglong2*)(Whh + (size_t)(rgrp * 32 + w * 4 + r) * H_);
#pragma unroll
        for (int i = 0; i < 8; i++) wreg[r][i] = Wg[l + 32 * i];
    }

    // writer-lane identity: even lanes write output o=(l>>1)&15
    const bool wr   = (l & 1) == 0;
    const int  o    = (l >> 1) & 15;
    const int  ob   = bgrp * 4 + (o >> 2);            // batch
    const int  hrow = rgrp * 32 + w * 4 + (o & 3);    // global h row
    const float* WxhRow = Wxh + (size_t)hrow * V_;

    int* const ctr = &g_bar[bgrp * 32];               // hot line, one per group

    // prefetch e for t=0
    float e = 0.0f;
    if (wr) e = __ldg(WxhRow + __ldg(x_seq + ob * S_ + 0));

    const uint32_t sdst = smem_u32(hsm2);

    for (int t = 0; t < S_; t++) {
        if (t == 0) {
            // h0 == 0: write zeros directly (no gmem read, no init dependency)
            const ulonglong2 z = make_ulonglong2(0ull, 0ull);
#pragma unroll
            for (int ii = 0; ii < 4; ii++) hsm2[tid + 256 * ii] = z;
        } else {
            const char* hg = (const char*)g_hbuf[t & 1] + (size_t)bgrp * 4 * H_ * 4;
            // stage this group's 4 batches of h (16KB) in ONE cp.async group
#pragma unroll
            for (int ii = 0; ii < 4; ii++) {
                uint32_t off = (uint32_t)(tid + 256 * ii) * 16;
                asm volatile("cp.async.cg.shared.global [%0], [%1], 16;"
                             :: "r"(sdst + off), "l"(hg + off));
            }
        }
        asm volatile("cp.async.commit_group;");

        // prefetch next step's embedding (x -> Wxh chain resolves under compute)
        float e_next = 0.0f;
        if (wr && t + 1 < S_)
            e_next = __ldg(WxhRow + __ldg(x_seq + ob * S_ + (t + 1)));

        unsigned long long acc[16];
#pragma unroll
        for (int j = 0; j < 16; j++) acc[j] = 0ull;

        asm volatile("cp.async.wait_group 0;");
        __syncthreads();
#pragma unroll
        for (int i = 0; i < 8; i++) {
            ulonglong2 hv[4];
#pragma unroll
            for (int bi = 0; bi < 4; bi++)
                hv[bi] = hsm2[bi * 256 + l + 32 * i];
#pragma unroll
            for (int bi = 0; bi < 4; bi++)
#pragma unroll
                for (int ri = 0; ri < 4; ri++) {
                    ffma2(acc[bi * 4 + ri], hv[bi].x, wreg[ri][i].x);
                    ffma2(acc[bi * 4 + ri], hv[bi].y, wreg[ri][i].y);
                }
        }

        // merged butterfly: 16 sums over 32 lanes
        float vals[16];
#pragma unroll
        for (int j = 0; j < 16; j++) vals[j] = unpack_sum(acc[j]);
#pragma unroll
        for (int off = 16; off >= 2; off >>= 1) {
            bool hiSide = (l & off) != 0;
#pragma unroll
            for (int j = 0; j < 8; j++) {
                if (j < (off >> 1)) {
                    float send = hiSide ? vals[j] : vals[j + (off >> 1)];
                    float recv = __shfl_xor_sync(0xffffffffu, send, off);
                    float keep = hiSide ? vals[j + (off >> 1)] : vals[j];
                    vals[j] = keep + recv;
                }
            }
        }
        vals[0] += __shfl_xor_sync(0xffffffffu, vals[0], 1);

        float hn = 0.0f;
        if (wr) {
            hn = fw_tanh(vals[0] + e);
            if (t < S_ - 1)
                g_hbuf[(t + 1) & 1][ob * H_ + hrow] = hn;   // critical-path publish
            else
                out_tail[ob * H_ + hrow] = hn;              // h_final direct write
        }
        e = e_next;

        if (t < S_ - 1) {
            // per-group barrier: rally; tid0 release-arrives; deferred work; poll; release
            __syncthreads();                    // CTA h-stores happen-before tid0's release
            if (tid == 0) {
                asm volatile("red.release.gpu.global.add.s32 [%0], 1;"
                             :: "l"(ctr) : "memory");
            }
            // deferred off-critical-path work inside the wait window
            if (wr) g_Hall[((size_t)(ob * S_ + t)) * H_ + hrow] = __float2half(hn);
            if (tid == 0) {
                const int target = 32 * (t + 1);           // monotonic counter
                int v;
                do {
                    asm volatile("ld.acquire.gpu.global.s32 %0, [%1];"
                                 : "=r"(v) : "l"(ctr) : "memory");
                } while (v < target);
            }
            __syncthreads();                    // broadcast release
        } else {
            if (wr) g_Hall[((size_t)(ob * S_ + t)) * H_ + hrow] = __float2half(hn);
        }
    }
}

// ---------------- GEMM: logits[4096,32000] = Hall @ W16^T (fp16 in, fp32 acc) ----
// R10 proven config: grid 8000 (m fast), CTA tile 128x128, BK=64, 3-stage
// cp.async (96KB, 2 CTA/SM), single-sync multistage ordering.
static constexpr int BKB    = 128;            // bytes per smem row (64 fp16)
static constexpr int ASZ    = 128 * BKB;      // 16 KB per operand tile
static constexpr int STAGE  = 2 * ASZ;        // 32 KB per stage
static constexpr int STAGES = 3;              // 96 KB dynamic smem

__global__ __launch_bounds__(256, 2) void gemm_hmma(float* __restrict__ out) {
    extern __shared__ char smc[];
    const int tid  = threadIdx.x;
    const int lane = tid & 31;
    const int warp = tid >> 5;
    const int wm   = warp >> 2;   // 0..1
    const int wn   = warp & 3;    // 0..3
    const int m0   = blockIdx.x * 128;   // m fast -> consecutive CTAs share B tile
    const int n0   = blockIdx.y * 128;
    const uint32_t sbase = smem_u32(smc);

    const char* Agb = (const char*)g_Hall + (size_t)m0 * (H_ * 2);
    const char* Bgb = (const char*)g_W16  + (size_t)n0 * (H_ * 2);

    auto issue = [&](int kb) {
        if (kb < 16) {
            uint32_t sa = sbase + (kb % STAGES) * STAGE;
            const char* Ag = Agb + kb * 128;
            const char* Bg = Bgb + kb * 128;
#pragma unroll
            for (int i = 0; i < 4; i++) {
                int chunk = tid + i * 256;
                int row = chunk >> 3, col = chunk & 7;
                uint32_t so = SW128((uint32_t)(row * BKB + col * 16));
                uint32_t d1 = sa + so;
                const char* g1 = Ag + (size_t)row * (H_ * 2) + col * 16;
                asm volatile("cp.async.cg.shared.global [%0], [%1], 16;" :: "r"(d1), "l"(g1));
                uint32_t d2 = sa + ASZ + so;
                const char* g2 = Bg + (size_t)row * (H_ * 2) + col * 16;
                asm volatile("cp.async.cg.shared.global [%0], [%1], 16;" :: "r"(d2), "l"(g2));
            }
        }
        asm volatile("cp.async.commit_group;");
    };

    issue(0); issue(1);

    float acc[4][4][4];
#pragma unroll
    for (int mi = 0; mi < 4; mi++)
#pragma unroll
        for (int ni = 0; ni < 4; ni++)
#pragma unroll
            for (int r = 0; r < 4; r++) acc[mi][ni][r] = 0.0f;

    for (int kb = 0; kb < 16; kb++) {
        asm volatile("cp.async.wait_group 1;");   // group kb complete
        __syncthreads();                          // stage kb visible to all

        uint32_t sa = sbase + (kb % STAGES) * STAGE;
        uint32_t sb = sa + ASZ;

#pragma unroll
        for (int kk = 0; kk < 4; kk++) {
            uint32_t a[4][4];
#pragma unroll
            for (int mi = 0; mi < 4; mi++) {
                int row   = wm * 64 + mi * 16 + (lane & 15);
                int chunk = kk * 2 + (lane >> 4);
                uint32_t addr = sa + SW128((uint32_t)(row * BKB + chunk * 16));
                asm volatile("ldmatrix.sync.aligned.m8n8.x4.shared.b16 {%0,%1,%2,%3}, [%4];"
                             : "=r"(a[mi][0]), "=r"(a[mi][1]), "=r"(a[mi][2]), "=r"(a[mi][3])
                             : "r"(addr));
            }
            uint32_t b[4][2];
#pragma unroll
            for (int nj = 0; nj < 2; nj++) {
                int row   = wn * 32 + nj * 16 + ((lane >> 4) & 1) * 8 + (lane & 7);
                int chunk = kk * 2 + ((lane >> 3) & 1);
                uint32_t addr = sb + SW128((uint32_t)(row * BKB + chunk * 16));
                uint32_t r0, r1, r2, r3;
                asm volatile("ldmatrix.sync.aligned.m8n8.x4.shared.b16 {%0,%1,%2,%3}, [%4];"
                             : "=r"(r0), "=r"(r1), "=r"(r2), "=r"(r3) : "r"(addr));
                b[2 * nj][0] = r0; b[2 * nj][1] = r1;
                b[2 * nj + 1][0] = r2; b[2 * nj + 1][1] = r3;
            }
#pragma unroll
            for (int mi = 0; mi < 4; mi++)
#pragma unroll
                for (int ni = 0; ni < 4; ni++)
                    asm volatile(
                        "mma.sync.aligned.m16n8k16.row.col.f32.f16.f16.f32 "
                        "{%0,%1,%2,%3}, {%4,%5,%6,%7}, {%8,%9}, {%0,%1,%2,%3};"
                        : "+f"(acc[mi][ni][0]), "+f"(acc[mi][ni][1]),
                          "+f"(acc[mi][ni][2]), "+f"(acc[mi][ni][3])
                        : "r"(a[mi][0]), "r"(a[mi][1]), "r"(a[mi][2]), "r"(a[mi][3]),
                          "r"(b[ni][0]), "r"(b[ni][1]));
        }

        // issue into stage (kb+2)%3 == (kb-1)%3: all warps finished reading it
        // before this iteration's __syncthreads (they completed compute kb-1).
        issue(kb + 2);
    }

    // epilogue: direct fp32 stores
#pragma unroll
    for (int mi = 0; mi < 4; mi++) {
        int row = m0 + wm * 64 + mi * 16 + (lane >> 2);
#pragma unroll
        for (int ni = 0; ni < 4; ni++) {
            int col = n0 + wn * 32 + ni * 8 + 2 * (lane & 3);
            float* p = out + (size_t)row * V_ + col;
            *(float2*)p                    = make_float2(acc[mi][ni][0], acc[mi][ni][1]);
            *(float2*)(p + 8 * (size_t)V_) = make_float2(acc[mi][ni][2], acc[mi][ni][3]);
        }
    }
}

// ---------------- launch ----------------
extern "C" void kernel_launch(void* const* d_in, const int* in_sizes, int n_in,
                              void* d_out, int out_size) {
    const int*   x_seq = (const int*)d_in[0];
    const float* Wxh   = (const float*)d_in[1];
    const float* Whh   = (const float*)d_in[2];
    const float* Why   = (const float*)d_in[3];
    float* out = (float*)d_out;

    cudaFuncSetAttribute(gemm_hmma, cudaFuncAttributeMaxDynamicSharedMemorySize,
                         STAGES * STAGE);

    init_kernel<<<1, 128>>>();

    rnn_persist<<<RNN_CTAS + CVT_CTAS, 256, 4 * H_ * sizeof(float)>>>(
        x_seq, Wxh, Whh, Why, out + (size_t)B_ * S_ * V_);

    dim3 grid((B_ * S_) / 128, V_ / 128);  // (32, 250): m fast
    gemm_hmma<<<grid, 256, STAGES * STAGE>>>(out);
}

// round 16
// speedup vs baseline: 1.0179x; 1.0179x over previous
#include <cuda_runtime.h>
#include <cuda_fp16.h>
#include <cstdint>

// Problem dims
#define B_ 16
#define S_ 256
#define V_ 32000
#define H_ 1024

// ---------------- scratch (device globals — no runtime alloc) ----------------
__device__ __align__(256) float  g_hbuf[2][B_ * H_];              // ping-pong hidden state
__device__ __align__(256) __half g_Hall[B_ * S_ * H_];            // all h_t, fp16 (8 MB)
__device__ __align__(256) __half g_W16[(size_t)V_ * H_];          // Why in fp16 (64 MB)
__device__ __align__(256) int g_bar[4 * 32];                      // 4 monotonic group counters, 128B apart

// ---------------- helpers ----------------
__device__ __forceinline__ uint32_t smem_u32(const void* p) {
    uint32_t a;
    asm("{ .reg .u64 t; cvta.to.shared.u64 t, %1; cvt.u32.u64 %0, t; }" : "=r"(a) : "l"(p));
    return a;
}
#define SW128(off) ((off) ^ (((off) >> 3) & 0x70))

__device__ __forceinline__ void ffma2(unsigned long long& d, unsigned long long a,
                                      unsigned long long b) {
    asm("fma.rn.f32x2 %0, %1, %2, %0;" : "+l"(d) : "l"(a), "l"(b));
}
__device__ __forceinline__ float unpack_sum(unsigned long long v) {
    float lo, hi;
    asm("mov.b64 {%0, %1}, %2;" : "=f"(lo), "=f"(hi) : "l"(v));
    return lo + hi;
}

__device__ __forceinline__ float fw_tanh(float x) {
    const float BP = 8192.0f / 32767.0f;
    float xc = fminf(fmaxf(x, -1.0f), 1.0f);
    float a = fabsf(xc);
    return (a < BP) ? xc : copysignf(BP + (a - BP) * 0.75f, xc);
}

// ---------------- kernel: init (zero the 4 group counters only) -------------
__global__ void init_kernel() {
    int i = blockIdx.x * blockDim.x + threadIdx.x;
    if (i < 4 * 32) g_bar[i] = 0;
}

// ---------------- persistent recurrence kernel (v11) -------------------------
// Grid 148 CTAs x 256 threads (1/SM).
//   CTAs 0..127 : recurrence. CTA c: batch group bgrp=c&3, row group rgrp=c>>2.
//                 Monotonic per-group counters; tid0 release-arrive + poll.
//   CTAs 128..147: convert Why -> fp16 (g_W16) on otherwise-idle SMs, then exit.
//                 Kernel-end ordering makes g_W16 visible to the GEMM.
// t=0 uses zeros written to smem directly (h0 == 0), so g_hbuf needs no init.
#define RNN_CTAS 128
#define CVT_CTAS 20

__global__ __launch_bounds__(256, 1) void rnn_persist(const int* __restrict__ x_seq,
                                                      const float* __restrict__ Wxh,
                                                      const float* __restrict__ Whh,
                                                      const float* __restrict__ Why,
                                                      float* __restrict__ out_tail) {
    extern __shared__ float sm[];
    ulonglong2* hsm2 = (ulonglong2*)sm;          // [4][256] 16B units

    const int c    = blockIdx.x;
    const int tid  = threadIdx.x;

    // ---- spare-SM path: Why -> fp16 conversion ----
    if (c >= RNN_CTAS) {
        const size_t n4 = (size_t)V_ * H_ / 4;
        const float4* in = (const float4*)Why;
        __half2* o16 = (__half2*)g_W16;
        for (size_t i = (size_t)(c - RNN_CTAS) * 256 + tid; i < n4;
             i += (size_t)CVT_CTAS * 256) {
            float4 v = __ldg(&in[i]);
            o16[2 * i]     = __floats2half2_rn(v.x, v.y);
            o16[2 * i + 1] = __floats2half2_rn(v.z, v.w);
        }
        return;
    }

    // ---- recurrence path ----
    const int w    = tid >> 5;
    const int l    = tid & 31;
    const int bgrp = c & 3;        // batches bgrp*4 .. bgrp*4+3
    const int rgrp = c >> 2;       // rows rgrp*32 .. rgrp*32+31

    // Whh slice -> registers: 4 rows x 8 k-units (16B each) = 128 regs
    ulonglong2 wreg[4][8];
#pragma unroll
    for (int r = 0; r < 4; r++) {
        const ulonglong2* Wg =
            (const ulonglong2*)(Whh + (size_t)(rgrp * 32 + w * 4 + r) * H_);
#pragma unroll
        for (int i = 0; i < 8; i++) wreg[r][i] = Wg[l + 32 * i];
    }

    // writer-lane identity: even lanes write output o=(l>>1)&15
    const bool wr   = (l & 1) == 0;
    const int  o    = (l >> 1) & 15;
    const int  ob   = bgrp * 4 + (o >> 2);            // batch
    const int  hrow = rgrp * 32 + w * 4 + (o & 3);    // global h row
    const float* WxhRow = Wxh + (size_t)hrow * V_;

    int* const ctr = &g_bar[bgrp * 32];               // hot line, one per group

    // prefetch e for t=0
    float e = 0.0f;
    if (wr) e = __ldg(WxhRow + __ldg(x_seq + ob * S_ + 0));

    const uint32_t sdst = smem_u32(hsm2);

    for (int t = 0; t < S_; t++) {
        if (t == 0) {
            // h0 == 0: write zeros directly (no gmem read, no init dependency)
            const ulonglong2 z = make_ulonglong2(0ull, 0ull);
#pragma unroll
            for (int ii = 0; ii < 4; ii++) hsm2[tid + 256 * ii] = z;
        } else {
            const char* hg = (const char*)g_hbuf[t & 1] + (size_t)bgrp * 4 * H_ * 4;
            // stage this group's 4 batches of h (16KB) in ONE cp.async group
#pragma unroll
            for (int ii = 0; ii < 4; ii++) {
                uint32_t off = (uint32_t)(tid + 256 * ii) * 16;
                asm volatile("cp.async.cg.shared.global [%0], [%1], 16;"
                             :: "r"(sdst + off), "l"(hg + off));
            }
        }
        asm volatile("cp.async.commit_group;");

        // prefetch next step's embedding (x -> Wxh chain resolves under compute)
        float e_next = 0.0f;
        if (wr && t + 1 < S_)
            e_next = __ldg(WxhRow + __ldg(x_seq + ob * S_ + (t + 1)));

        unsigned long long acc[16];
#pragma unroll
        for (int j = 0; j < 16; j++) acc[j] = 0ull;

        asm volatile("cp.async.wait_group 0;");
        __syncthreads();
#pragma unroll
        for (int i = 0; i < 8; i++) {
            ulonglong2 hv[4];
#pragma unroll
            for (int bi = 0; bi < 4; bi++)
                hv[bi] = hsm2[bi * 256 + l + 32 * i];
#pragma unroll
            for (int bi = 0; bi < 4; bi++)
#pragma unroll
                for (int ri = 0; ri < 4; ri++) {
                    ffma2(acc[bi * 4 + ri], hv[bi].x, wreg[ri][i].x);
                    ffma2(acc[bi * 4 + ri], hv[bi].y, wreg[ri][i].y);
                }
        }

        // merged butterfly: 16 sums over 32 lanes
        float vals[16];
#pragma unroll
        for (int j = 0; j < 16; j++) vals[j] = unpack_sum(acc[j]);
#pragma unroll
        for (int off = 16; off >= 2; off >>= 1) {
            bool hiSide = (l & off) != 0;
#pragma unroll
            for (int j = 0; j < 8; j++) {
                if (j < (off >> 1)) {
                    float send = hiSide ? vals[j] : vals[j + (off >> 1)];
                    float recv = __shfl_xor_sync(0xffffffffu, send, off);
                    float keep = hiSide ? vals[j + (off >> 1)] : vals[j];
                    vals[j] = keep + recv;
                }
            }
        }
        vals[0] += __shfl_xor_sync(0xffffffffu, vals[0], 1);

        float hn = 0.0f;
        if (wr) {
            hn = fw_tanh(vals[0] + e);
            if (t < S_ - 1)
                g_hbuf[(t + 1) & 1][ob * H_ + hrow] = hn;   // critical-path publish
            else
                out_tail[ob * H_ + hrow] = hn;              // h_final direct write
        }
        e = e_next;

        if (t < S_ - 1) {
            // per-group barrier: rally; tid0 release-arrives; deferred work; poll; release
            __syncthreads();                    // CTA h-stores happen-before tid0's release
            if (tid == 0) {
                asm volatile("red.release.gpu.global.add.s32 [%0], 1;"
                             :: "l"(ctr) : "memory");
            }
            // deferred off-critical-path work inside the wait window
            if (wr) g_Hall[((size_t)(ob * S_ + t)) * H_ + hrow] = __float2half(hn);
            if (tid == 0) {
                const int target = 32 * (t + 1);           // monotonic counter
                int v;
                do {
                    asm volatile("ld.acquire.gpu.global.s32 %0, [%1];"
                                 : "=r"(v) : "l"(ctr) : "memory");
                } while (v < target);
            }
            __syncthreads();                    // broadcast release
        } else {
            if (wr) g_Hall[((size_t)(ob * S_ + t)) * H_ + hrow] = __float2half(hn);
        }
    }
}

// ---------------- GEMM: logits[4096,32000] = Hall @ W16^T (fp16 in, fp32 acc) ----
// R10 proven config: grid 8000 (m fast), CTA tile 128x128, BK=64, 3-stage
// cp.async (96KB, 2 CTA/SM), single-sync multistage ordering.
static constexpr int BKB    = 128;            // bytes per smem row (64 fp16)
static constexpr int ASZ    = 128 * BKB;      // 16 KB per operand tile
static constexpr int STAGE  = 2 * ASZ;        // 32 KB per stage
static constexpr int STAGES = 3;              // 96 KB dynamic smem

__global__ __launch_bounds__(256, 2) void gemm_hmma(float* __restrict__ out) {
    extern __shared__ char smc[];
    const int tid  = threadIdx.x;
    const int lane = tid & 31;
    const int warp = tid >> 5;
    const int wm   = warp >> 2;   // 0..1
    const int wn   = warp & 3;    // 0..3
    const int m0   = blockIdx.x * 128;   // m fast -> consecutive CTAs share B tile
    const int n0   = blockIdx.y * 128;
    const uint32_t sbase = smem_u32(smc);

    const char* Agb = (const char*)g_Hall + (size_t)m0 * (H_ * 2);
    const char* Bgb = (const char*)g_W16  + (size_t)n0 * (H_ * 2);

    auto issue = [&](int kb) {
        if (kb < 16) {
            uint32_t sa = sbase + (kb % STAGES) * STAGE;
            const char* Ag = Agb + kb * 128;
            const char* Bg = Bgb + kb * 128;
#pragma unroll
            for (int i = 0; i < 4; i++) {
                int chunk = tid + i * 256;
                int row = chunk >> 3, col = chunk & 7;
                uint32_t so = SW128((uint32_t)(row * BKB + col * 16));
                uint32_t d1 = sa + so;
                const char* g1 = Ag + (size_t)row * (H_ * 2) + col * 16;
                asm volatile("cp.async.cg.shared.global [%0], [%1], 16;" :: "r"(d1), "l"(g1));
                uint32_t d2 = sa + ASZ + so;
                const char* g2 = Bg + (size_t)row * (H_ * 2) + col * 16;
                asm volatile("cp.async.cg.shared.global [%0], [%1], 16;" :: "r"(d2), "l"(g2));
            }
        }
        asm volatile("cp.async.commit_group;");
    };

    issue(0); issue(1);

    float acc[4][4][4];
#pragma unroll
    for (int mi = 0; mi < 4; mi++)
#pragma unroll
        for (int ni = 0; ni < 4; ni++)
#pragma unroll
            for (int r = 0; r < 4; r++) acc[mi][ni][r] = 0.0f;

    for (int kb = 0; kb < 16; kb++) {
        asm volatile("cp.async.wait_group 1;");   // group kb complete
        __syncthreads();                          // stage kb visible to all

        uint32_t sa = sbase + (kb % STAGES) * STAGE;
        uint32_t sb = sa + ASZ;

#pragma unroll
        for (int kk = 0; kk < 4; kk++) {
            uint32_t a[4][4];
#pragma unroll
            for (int mi = 0; mi < 4; mi++) {
                int row   = wm * 64 + mi * 16 + (lane & 15);
                int chunk = kk * 2 + (lane >> 4);
                uint32_t addr = sa + SW128((uint32_t)(row * BKB + chunk * 16));
                asm volatile("ldmatrix.sync.aligned.m8n8.x4.shared.b16 {%0,%1,%2,%3}, [%4];"
                             : "=r"(a[mi][0]), "=r"(a[mi][1]), "=r"(a[mi][2]), "=r"(a[mi][3])
                             : "r"(addr));
            }
            uint32_t b[4][2];
#pragma unroll
            for (int nj = 0; nj < 2; nj++) {
                int row   = wn * 32 + nj * 16 + ((lane >> 4) & 1) * 8 + (lane & 7);
                int chunk = kk * 2 + ((lane >> 3) & 1);
                uint32_t addr = sb + SW128((uint32_t)(row * BKB + chunk * 16));
                uint32_t r0, r1, r2, r3;
                asm volatile("ldmatrix.sync.aligned.m8n8.x4.shared.b16 {%0,%1,%2,%3}, [%4];"
                             : "=r"(r0), "=r"(r1), "=r"(r2), "=r"(r3) : "r"(addr));
                b[2 * nj][0] = r0; b[2 * nj][1] = r1;
                b[2 * nj + 1][0] = r2; b[2 * nj + 1][1] = r3;
            }
#pragma unroll
            for (int mi = 0; mi < 4; mi++)
#pragma unroll
                for (int ni = 0; ni < 4; ni++)
                    asm volatile(
                        "mma.sync.aligned.m16n8k16.row.col.f32.f16.f16.f32 "
                        "{%0,%1,%2,%3}, {%4,%5,%6,%7}, {%8,%9}, {%0,%1,%2,%3};"
                        : "+f"(acc[mi][ni][0]), "+f"(acc[mi][ni][1]),
                          "+f"(acc[mi][ni][2]), "+f"(acc[mi][ni][3])
                        : "r"(a[mi][0]), "r"(a[mi][1]), "r"(a[mi][2]), "r"(a[mi][3]),
                          "r"(b[ni][0]), "r"(b[ni][1]));
        }

        // issue into stage (kb+2)%3 == (kb-1)%3: all warps finished reading it
        // before this iteration's __syncthreads (they completed compute kb-1).
        issue(kb + 2);
    }

    // epilogue: direct fp32 stores
#pragma unroll
    for (int mi = 0; mi < 4; mi++) {
        int row = m0 + wm * 64 + mi * 16 + (lane >> 2);
#pragma unroll
        for (int ni = 0; ni < 4; ni++) {
            int col = n0 + wn * 32 + ni * 8 + 2 * (lane & 3);
            float* p = out + (size_t)row * V_ + col;
            *(float2*)p                    = make_float2(acc[mi][ni][0], acc[mi][ni][1]);
            *(float2*)(p + 8 * (size_t)V_) = make_float2(acc[mi][ni][2], acc[mi][ni][3]);
        }
    }
}

// ---------------- launch ----------------
extern "C" void kernel_launch(void* const* d_in, const int* in_sizes, int n_in,
                              void* d_out, int out_size) {
    const int*   x_seq = (const int*)d_in[0];
    const float* Wxh   = (const float*)d_in[1];
    const float* Whh   = (const float*)d_in[2];
    const float* Why   = (const float*)d_in[3];
    float* out = (float*)d_out;

    cudaFuncSetAttribute(gemm_hmma, cudaFuncAttributeMaxDynamicSharedMemorySize,
                         STAGES * STAGE);

    init_kernel<<<1, 128>>>();

    rnn_persist<<<RNN_CTAS + CVT_CTAS, 256, 4 * H_ * sizeof(float)>>>(
        x_seq, Wxh, Whh, Why, out + (size_t)B_ * S_ * V_);

    dim3 grid((B_ * S_) / 128, V_ / 128);  // (32, 250): m fast
    gemm_hmma<<<grid, 256, STAGES * STAGE>>>(out);
}

// round 17
// speedup vs baseline: 1.0291x; 1.0110x over previous
#include <cuda_runtime.h>
#include <cuda_fp16.h>
#include <cstdint>

// Problem dims
#define B_ 16
#define S_ 256
#define V_ 32000
#define H_ 1024

// ---------------- scratch (device globals — no runtime alloc) ----------------
__device__ __align__(256) float  g_hbuf[2][B_ * H_];              // ping-pong hidden state
__device__ __align__(256) __half g_Hall[B_ * S_ * H_];            // all h_t, fp16 (8 MB)
__device__ __align__(256) __half g_W16[(size_t)V_ * H_];          // Why in fp16 (64 MB)
__device__ __align__(256) int g_bar[4 * 32];                      // 4 monotonic group counters, 128B apart (static-zeroed; reset by GEMM each run)

// ---------------- helpers ----------------
__device__ __forceinline__ uint32_t smem_u32(const void* p) {
    uint32_t a;
    asm("{ .reg .u64 t; cvta.to.shared.u64 t, %1; cvt.u32.u64 %0, t; }" : "=r"(a) : "l"(p));
    return a;
}
#define SW128(off) ((off) ^ (((off) >> 3) & 0x70))

__device__ __forceinline__ void ffma2(unsigned long long& d, unsigned long long a,
                                      unsigned long long b) {
    asm("fma.rn.f32x2 %0, %1, %2, %0;" : "+l"(d) : "l"(a), "l"(b));
}
__device__ __forceinline__ float unpack_sum(unsigned long long v) {
    float lo, hi;
    asm("mov.b64 {%0, %1}, %2;" : "=f"(lo), "=f"(hi) : "l"(v));
    return lo + hi;
}

__device__ __forceinline__ float fw_tanh(float x) {
    const float BP = 8192.0f / 32767.0f;
    float xc = fminf(fmaxf(x, -1.0f), 1.0f);
    float a = fabsf(xc);
    return (a < BP) ? xc : copysignf(BP + (a - BP) * 0.75f, xc);
}

// ---------------- persistent recurrence kernel (v11, frozen) -----------------
// Grid 148 CTAs x 256 threads (1/SM).
//   CTAs 0..127 : recurrence. CTA c: batch group bgrp=c&3, row group rgrp=c>>2.
//                 Monotonic per-group counters; tid0 release-arrive + poll.
//   CTAs 128..147: convert Why -> fp16 (g_W16) on otherwise-idle SMs, then exit.
// t=0 writes zeros to smem directly (h0 == 0). Counters are zeroed by the
// PREVIOUS run's GEMM (or static init on the very first run).
#define RNN_CTAS 128
#define CVT_CTAS 20

__global__ __launch_bounds__(256, 1) void rnn_persist(const int* __restrict__ x_seq,
                                                      const float* __restrict__ Wxh,
                                                      const float* __restrict__ Whh,
                                                      const float* __restrict__ Why,
                                                      float* __restrict__ out_tail) {
    extern __shared__ float sm[];
    ulonglong2* hsm2 = (ulonglong2*)sm;          // [4][256] 16B units

    const int c    = blockIdx.x;
    const int tid  = threadIdx.x;

    // ---- spare-SM path: Why -> fp16 conversion ----
    if (c >= RNN_CTAS) {
        const size_t n4 = (size_t)V_ * H_ / 4;
        const float4* in = (const float4*)Why;
        __half2* o16 = (__half2*)g_W16;
        for (size_t i = (size_t)(c - RNN_CTAS) * 256 + tid; i < n4;
             i += (size_t)CVT_CTAS * 256) {
            float4 v = __ldg(&in[i]);
            o16[2 * i]     = __floats2half2_rn(v.x, v.y);
            o16[2 * i + 1] = __floats2half2_rn(v.z, v.w);
        }
        return;
    }

    // ---- recurrence path ----
    const int w    = tid >> 5;
    const int l    = tid & 31;
    const int bgrp = c & 3;        // batches bgrp*4 .. bgrp*4+3
    const int rgrp = c >> 2;       // rows rgrp*32 .. rgrp*32+31

    // Whh slice -> registers: 4 rows x 8 k-units (16B each) = 128 regs
    ulonglong2 wreg[4][8];
#pragma unroll
    for (int r = 0; r < 4; r++) {
        const ulonglong2* Wg =
            (const ulonglong2*)(Whh + (size_t)(rgrp * 32 + w * 4 + r) * H_);
#pragma unroll
        for (int i = 0; i < 8; i++) wreg[r][i] = Wg[l + 32 * i];
    }

    // writer-lane identity: even lanes write output o=(l>>1)&15
    const bool wr   = (l & 1) == 0;
    const int  o    = (l >> 1) & 15;
    const int  ob   = bgrp * 4 + (o >> 2);            // batch
    const int  hrow = rgrp * 32 + w * 4 + (o & 3);    // global h row
    const float* WxhRow = Wxh + (size_t)hrow * V_;

    int* const ctr = &g_bar[bgrp * 32];               // hot line, one per group

    // prefetch e for t=0
    float e = 0.0f;
    if (wr) e = __ldg(WxhRow + __ldg(x_seq + ob * S_ + 0));

    const uint32_t sdst = smem_u32(hsm2);

    for (int t = 0; t < S_; t++) {
        if (t == 0) {
            // h0 == 0: write zeros directly (no gmem read, no init dependency)
            const ulonglong2 z = make_ulonglong2(0ull, 0ull);
#pragma unroll
            for (int ii = 0; ii < 4; ii++) hsm2[tid + 256 * ii] = z;
        } else {
            const char* hg = (const char*)g_hbuf[t & 1] + (size_t)bgrp * 4 * H_ * 4;
            // stage this group's 4 batches of h (16KB) in ONE cp.async group
#pragma unroll
            for (int ii = 0; ii < 4; ii++) {
                uint32_t off = (uint32_t)(tid + 256 * ii) * 16;
                asm volatile("cp.async.cg.shared.global [%0], [%1], 16;"
                             :: "r"(sdst + off), "l"(hg + off));
            }
        }
        asm volatile("cp.async.commit_group;");

        // prefetch next step's embedding (x -> Wxh chain resolves under compute)
        float e_next = 0.0f;
        if (wr && t + 1 < S_)
            e_next = __ldg(WxhRow + __ldg(x_seq + ob * S_ + (t + 1)));

        unsigned long long acc[16];
#pragma unroll
        for (int j = 0; j < 16; j++) acc[j] = 0ull;

        asm volatile("cp.async.wait_group 0;");
        __syncthreads();
#pragma unroll
        for (int i = 0; i < 8; i++) {
            ulonglong2 hv[4];
#pragma unroll
            for (int bi = 0; bi < 4; bi++)
                hv[bi] = hsm2[bi * 256 + l + 32 * i];
#pragma unroll
            for (int bi = 0; bi < 4; bi++)
#pragma unroll
                for (int ri = 0; ri < 4; ri++) {
                    ffma2(acc[bi * 4 + ri], hv[bi].x, wreg[ri][i].x);
                    ffma2(acc[bi * 4 + ri], hv[bi].y, wreg[ri][i].y);
                }
        }

        // merged butterfly: 16 sums over 32 lanes
        float vals[16];
#pragma unroll
        for (int j = 0; j < 16; j++) vals[j] = unpack_sum(acc[j]);
#pragma unroll
        for (int off = 16; off >= 2; off >>= 1) {
            bool hiSide = (l & off) != 0;
#pragma unroll
            for (int j = 0; j < 8; j++) {
                if (j < (off >> 1)) {
                    float send = hiSide ? vals[j] : vals[j + (off >> 1)];
                    float recv = __shfl_xor_sync(0xffffffffu, send, off);
                    float keep = hiSide ? vals[j + (off >> 1)] : vals[j];
                    vals[j] = keep + recv;
                }
            }
        }
        vals[0] += __shfl_xor_sync(0xffffffffu, vals[0], 1);

        float hn = 0.0f;
        if (wr) {
            hn = fw_tanh(vals[0] + e);
            if (t < S_ - 1)
                g_hbuf[(t + 1) & 1][ob * H_ + hrow] = hn;   // critical-path publish
            else
                out_tail[ob * H_ + hrow] = hn;              // h_final direct write
        }
        e = e_next;

        if (t < S_ - 1) {
            // per-group barrier: rally; tid0 release-arrives; deferred work; poll; release
            __syncthreads();                    // CTA h-stores happen-before tid0's release
            if (tid == 0) {
                asm volatile("red.release.gpu.global.add.s32 [%0], 1;"
                             :: "l"(ctr) : "memory");
            }
            // deferred off-critical-path work inside the wait window
            if (wr) g_Hall[((size_t)(ob * S_ + t)) * H_ + hrow] = __float2half(hn);
            if (tid == 0) {
                const int target = 32 * (t + 1);           // monotonic counter
                int v;
                do {
                    asm volatile("ld.acquire.gpu.global.s32 %0, [%1];"
                                 : "=r"(v) : "l"(ctr) : "memory");
                } while (v < target);
            }
            __syncthreads();                    // broadcast release
        } else {
            if (wr) g_Hall[((size_t)(ob * S_ + t)) * H_ + hrow] = __float2half(hn);
        }
    }
}

// ---------------- GEMM v4: logits[4096,32000] = Hall @ W16^T ------------------
// CTA tile 128x128, **4 warps of 64x64** (128 threads) — halves ldmatrix bytes
// per MAC (L1 was co-bound with tensor at 8x 64x32 warps). BK=64, 3-stage
// cp.async (96KB, 2 CTA/SM preserved), single-sync multistage ordering.
// Also zeroes the 4 rnn barrier counters (runs after rnn in stream order).
static constexpr int BKB    = 128;            // bytes per smem row (64 fp16)
static constexpr int ASZ    = 128 * BKB;      // 16 KB per operand tile
static constexpr int STAGE  = 2 * ASZ;        // 32 KB per stage
static constexpr int STAGES = 3;              // 96 KB dynamic smem

__global__ __launch_bounds__(128, 2) void gemm_hmma(float* __restrict__ out) {
    extern __shared__ char smc[];
    const int tid  = threadIdx.x;
    const int lane = tid & 31;
    const int warp = tid >> 5;    // 0..3
    const int wm   = warp >> 1;   // 0..1
    const int wn   = warp & 1;    // 0..1
    const int m0   = blockIdx.x * 128;   // m fast -> consecutive CTAs share B tile
    const int n0   = blockIdx.y * 128;
    const uint32_t sbase = smem_u32(smc);

    // reset rnn barrier counters for the next graph replay (rnn already done)
    if (blockIdx.x == 0 && blockIdx.y == 0 && tid < 4) g_bar[tid * 32] = 0;

    const char* Agb = (const char*)g_Hall + (size_t)m0 * (H_ * 2);
    const char* Bgb = (const char*)g_W16  + (size_t)n0 * (H_ * 2);

    auto issue = [&](int kb) {
        if (kb < 16) {
            uint32_t sa = sbase + (kb % STAGES) * STAGE;
            const char* Ag = Agb + kb * 128;
            const char* Bg = Bgb + kb * 128;
#pragma unroll
            for (int i = 0; i < 8; i++) {
                int chunk = tid + i * 128;             // 0..1023
                int row = chunk >> 3, col = chunk & 7;
                uint32_t so = SW128((uint32_t)(row * BKB + col * 16));
                const char* g1 = Ag + (size_t)row * (H_ * 2) + col * 16;
                asm volatile("cp.async.cg.shared.global [%0], [%1], 16;"
                             :: "r"(sa + so), "l"(g1));
                const char* g2 = Bg + (size_t)row * (H_ * 2) + col * 16;
                asm volatile("cp.async.cg.shared.global [%0], [%1], 16;"
                             :: "r"(sa + ASZ + so), "l"(g2));
            }
        }
        asm volatile("cp.async.commit_group;");
    };

    issue(0); issue(1);

    float acc[4][8][4];
#pragma unroll
    for (int mi = 0; mi < 4; mi++)
#pragma unroll
        for (int ni = 0; ni < 8; ni++)
#pragma unroll
            for (int r = 0; r < 4; r++) acc[mi][ni][r] = 0.0f;

    for (int kb = 0; kb < 16; kb++) {
        asm volatile("cp.async.wait_group 1;");   // group kb complete
        __syncthreads();                          // stage kb visible to all

        uint32_t sa = sbase + (kb % STAGES) * STAGE;
        uint32_t sb = sa + ASZ;

#pragma unroll
        for (int kk = 0; kk < 4; kk++) {
            uint32_t a[4][4];
#pragma unroll
            for (int mi = 0; mi < 4; mi++) {
                int row   = wm * 64 + mi * 16 + (lane & 15);
                int chunk = kk * 2 + (lane >> 4);
                uint32_t addr = sa + SW128((uint32_t)(row * BKB + chunk * 16));
                asm volatile("ldmatrix.sync.aligned.m8n8.x4.shared.b16 {%0,%1,%2,%3}, [%4];"
                             : "=r"(a[mi][0]), "=r"(a[mi][1]), "=r"(a[mi][2]), "=r"(a[mi][3])
                             : "r"(addr));
            }
            uint32_t b[8][2];
#pragma unroll
            for (int nj = 0; nj < 4; nj++) {
                int row   = wn * 64 + nj * 16 + ((lane >> 4) & 1) * 8 + (lane & 7);
                int chunk = kk * 2 + ((lane >> 3) & 1);
                uint32_t addr = sb + SW128((uint32_t)(row * BKB + chunk * 16));
                uint32_t r0, r1, r2, r3;
                asm volatile("ldmatrix.sync.aligned.m8n8.x4.shared.b16 {%0,%1,%2,%3}, [%4];"
                             : "=r"(r0), "=r"(r1), "=r"(r2), "=r"(r3) : "r"(addr));
                b[2 * nj][0] = r0; b[2 * nj][1] = r1;
                b[2 * nj + 1][0] = r2; b[2 * nj + 1][1] = r3;
            }
#pragma unroll
            for (int mi = 0; mi < 4; mi++)
#pragma unroll
                for (int ni = 0; ni < 8; ni++)
                    asm volatile(
                        "mma.sync.aligned.m16n8k16.row.col.f32.f16.f16.f32 "
                        "{%0,%1,%2,%3}, {%4,%5,%6,%7}, {%8,%9}, {%0,%1,%2,%3};"
                        : "+f"(acc[mi][ni][0]), "+f"(acc[mi][ni][1]),
                          "+f"(acc[mi][ni][2]), "+f"(acc[mi][ni][3])
                        : "r"(a[mi][0]), "r"(a[mi][1]), "r"(a[mi][2]), "r"(a[mi][3]),
                          "r"(b[ni][0]), "r"(b[ni][1]));
        }

        // issue into stage (kb+2)%3 == (kb-1)%3: all warps finished reading it
        // before this iteration's __syncthreads (they completed compute kb-1).
        issue(kb + 2);
    }

    // epilogue: direct fp32 stores
#pragma unroll
    for (int mi = 0; mi < 4; mi++) {
        int row = m0 + wm * 64 + mi * 16 + (lane >> 2);
#pragma unroll
        for (int ni = 0; ni < 8; ni++) {
            int col = n0 + wn * 64 + ni * 8 + 2 * (lane & 3);
            float* p = out + (size_t)row * V_ + col;
            *(float2*)p                    = make_float2(acc[mi][ni][0], acc[mi][ni][1]);
            *(float2*)(p + 8 * (size_t)V_) = make_float2(acc[mi][ni][2], acc[mi][ni][3]);
        }
    }
}

// ---------------- launch ----------------
extern "C" void kernel_launch(void* const* d_in, const int* in_sizes, int n_in,
                              void* d_out, int out_size) {
    const int*   x_seq = (const int*)d_in[0];
    const float* Wxh   = (const float*)d_in[1];
    const float* Whh   = (const float*)d_in[2];
    const float* Why   = (const float*)d_in[3];
    float* out = (float*)d_out;

    cudaFuncSetAttribute(gemm_hmma, cudaFuncAttributeMaxDynamicSharedMemorySize,
                         STAGES * STAGE);

    rnn_persist<<<RNN_CTAS + CVT_CTAS, 256, 4 * H_ * sizeof(float)>>>(
        x_seq, Wxh, Whh, Why, out + (size_t)B_ * S_ * V_);

    dim3 grid((B_ * S_) / 128, V_ / 128);  // (32, 250): m fast
    gemm_hmma<<<grid, 128, STAGES * STAGE>>>(out);
}